// round 2
// baseline (speedup 1.0000x reference)
#include <cuda_runtime.h>
#include <cstdint>

// Problem dims
#define B_ROWS 8192
#define KDIM   4096
#define NDIM   4096
#define CAPQ   492

// GEMM tiling
#define BM 256
#define BN 128
#define BK 32
#define STAGES 4
#define MT (B_ROWS / BM)              // 32
#define NT (NDIM / BN)                // 32
#define KT (KDIM / BK)                // 128
#define A_BYTES (BM * BK * 4)         // 32768
#define B_BYTES (BN * BK * 4)         // 16384
#define STAGE_BYTES (A_BYTES + B_BYTES)
#define SMEM_SIZE (STAGES * STAGE_BYTES)   // 196608
#define GROUP_N 8

// Scratch (allocations forbidden -> __device__ globals)
__device__ float g_W[(size_t)NDIM * KDIM];    // dense W, tf32-rounded, [n][k]
__device__ float g_xr[(size_t)B_ROWS * KDIM]; // tf32-rounded x, [m][k]

__device__ __forceinline__ float f2tf32(float f) {
    uint32_t u;
    asm("cvt.rna.tf32.f32 %0, %1;" : "=r"(u) : "f"(f));
    return __uint_as_float(u);
}

// -------------------------------------------------------------- pre-kernels --
__global__ void round_x_kernel(const float4* __restrict__ x) {
    const size_t n4 = (size_t)B_ROWS * KDIM / 4;
    float4* o = (float4*)g_xr;
    for (size_t i = (size_t)blockIdx.x * blockDim.x + threadIdx.x; i < n4;
         i += (size_t)gridDim.x * blockDim.x) {
        float4 v = x[i];
        v.x = f2tf32(v.x); v.y = f2tf32(v.y); v.z = f2tf32(v.z); v.w = f2tf32(v.w);
        o[i] = v;
    }
}
__global__ void zero_w_kernel() {
    const size_t n4 = (size_t)NDIM * KDIM / 4;
    float4* o = (float4*)g_W;
    const float4 z = make_float4(0.f, 0.f, 0.f, 0.f);
    for (size_t i = (size_t)blockIdx.x * blockDim.x + threadIdx.x; i < n4;
         i += (size_t)gridDim.x * blockDim.x) {
        o[i] = z;
    }
}
__global__ void scatter_kernel(const float* __restrict__ values, const int* __restrict__ col) {
    int i = blockIdx.x * blockDim.x + threadIdx.x;
    if (i >= NDIM * CAPQ) return;
    float v = values[i];
    if (v != 0.0f) {
        int o = i / CAPQ;
        int c = col[i];
        atomicAdd(&g_W[(size_t)o * KDIM + c], f2tf32(v));
    }
}

// --------------------------------------------------------------- GEMM kernel -
// 256 threads = 8 warps in 4(M) x 2(N); warp tile 64x64; mma.sync m16n8k8 tf32.
// Smem tiles: A [BM][BK], B [BN][BK], both K-contiguous 128B rows with XOR
// swizzle: chunk16B ^= (row & 7). Both fragments loaded via ldmatrix.x4.b16
// (tf32 = one 32-bit word per thread per 8x4-f32 piece).
__global__ __launch_bounds__(256, 1)
void gemm_kernel(const float* __restrict__ bias, float* __restrict__ y)
{
    extern __shared__ __align__(128) unsigned char smem[];
    const uint32_t sbase = (uint32_t)__cvta_generic_to_shared(smem);
    const int tid  = threadIdx.x;
    const int lane = tid & 31;
    const int wid  = tid >> 5;
    const int wm   = wid & 3;      // 0..3  (M)
    const int wn   = wid >> 2;     // 0..1  (N)

    // block swizzle: M fastest within groups of GROUP_N n-tiles
    const int pid    = blockIdx.x;
    const int group  = pid / (GROUP_N * MT);
    const int rem    = pid % (GROUP_N * MT);
    const int mt_blk = rem % MT;
    const int nt_blk = group * GROUP_N + rem / MT;
    const int m0 = mt_blk * BM;
    const int n0 = nt_blk * BN;

    const float* Ag = g_xr + (size_t)m0 * KDIM;
    const float* Bg = g_W  + (size_t)n0 * KDIM;

    auto load_stage = [&](int kt, int slot) {
        const uint32_t sa = sbase + slot * STAGE_BYTES;
        const uint32_t sb = sa + A_BYTES;
        const float* ga = Ag + kt * BK;
        const float* gb = Bg + kt * BK;
        #pragma unroll
        for (int i = 0; i < 8; i++) {            // A: 2048 16B chunks
            int chunk = i * 256 + tid;
            int r = chunk >> 3, c = chunk & 7;
            uint32_t so = sa + r * 128 + ((c ^ (r & 7)) << 4);
            const float* g = ga + (size_t)r * KDIM + c * 4;
            asm volatile("cp.async.cg.shared.global [%0], [%1], 16;" :: "r"(so), "l"(g));
        }
        #pragma unroll
        for (int i = 0; i < 4; i++) {            // B: 1024 16B chunks
            int chunk = i * 256 + tid;
            int r = chunk >> 3, c = chunk & 7;
            uint32_t so = sb + r * 128 + ((c ^ (r & 7)) << 4);
            const float* g = gb + (size_t)r * KDIM + c * 4;
            asm volatile("cp.async.cg.shared.global [%0], [%1], 16;" :: "r"(so), "l"(g));
        }
        asm volatile("cp.async.commit_group;" ::: "memory");
    };

    float acc[4][8][4];
    #pragma unroll
    for (int i = 0; i < 4; i++)
        #pragma unroll
        for (int j = 0; j < 8; j++)
            #pragma unroll
            for (int k = 0; k < 4; k++) acc[i][j][k] = 0.f;

    const int idx   = lane & 7;
    const int piece = lane >> 3;

    auto compute_stage = [&](int slot) {
        const uint32_t sa = sbase + slot * STAGE_BYTES;
        const uint32_t sb = sa + A_BYTES;
        #pragma unroll
        for (int ks = 0; ks < 4; ks++) {         // 4 x k8 per BK=32
            uint32_t b[16];
            #pragma unroll
            for (int q = 0; q < 4; q++) {        // 4 n16-groups = n64
                int r = wn * 64 + q * 16 + idx + ((piece >> 1) << 3);
                int c = 2 * ks + (piece & 1);
                uint32_t addr = sb + r * 128 + ((c ^ (r & 7)) << 4);
                asm volatile("ldmatrix.sync.aligned.m8n8.x4.shared.b16 {%0,%1,%2,%3}, [%4];"
                    : "=r"(b[q*4+0]), "=r"(b[q*4+1]), "=r"(b[q*4+2]), "=r"(b[q*4+3])
                    : "r"(addr));
            }
            #pragma unroll
            for (int mt = 0; mt < 4; mt++) {     // 4 m16-tiles = m64
                uint32_t a[4];
                int r = wm * 64 + mt * 16 + idx + ((piece & 1) << 3);
                int c = 2 * ks + (piece >> 1);
                uint32_t addr = sa + r * 128 + ((c ^ (r & 7)) << 4);
                asm volatile("ldmatrix.sync.aligned.m8n8.x4.shared.b16 {%0,%1,%2,%3}, [%4];"
                    : "=r"(a[0]), "=r"(a[1]), "=r"(a[2]), "=r"(a[3])
                    : "r"(addr));
                #pragma unroll
                for (int nt = 0; nt < 8; nt++) {
                    asm volatile(
                        "mma.sync.aligned.m16n8k8.row.col.f32.tf32.tf32.f32 "
                        "{%0,%1,%2,%3},{%4,%5,%6,%7},{%8,%9},{%0,%1,%2,%3};"
                        : "+f"(acc[mt][nt][0]), "+f"(acc[mt][nt][1]),
                          "+f"(acc[mt][nt][2]), "+f"(acc[mt][nt][3])
                        : "r"(a[0]), "r"(a[1]), "r"(a[2]), "r"(a[3]),
                          "r"(b[(nt >> 1) * 4 + (nt & 1) * 2]),
                          "r"(b[(nt >> 1) * 4 + (nt & 1) * 2 + 1]));
                }
            }
        }
    };

    #pragma unroll
    for (int s = 0; s < STAGES - 1; s++) load_stage(s, s);

    for (int kt = 0; kt < KT; kt++) {
        asm volatile("cp.async.wait_group 2;" ::: "memory");
        __syncthreads();
        if (kt + STAGES - 1 < KT) load_stage(kt + STAGES - 1, (kt + STAGES - 1) & 3);
        compute_stage(kt & 3);
    }

    // ---- epilogue ----
    const int g   = lane >> 2;
    const int tig = lane & 3;
    #pragma unroll
    for (int mt = 0; mt < 4; mt++) {
        const int row = m0 + wm * 64 + mt * 16 + g;
        #pragma unroll
        for (int nt = 0; nt < 8; nt++) {
            const int col = n0 + wn * 64 + nt * 8 + tig * 2;
            const float b0 = __ldg(bias + col), b1 = __ldg(bias + col + 1);
            float2 v0 = make_float2(acc[mt][nt][0] + b0, acc[mt][nt][1] + b1);
            float2 v1 = make_float2(acc[mt][nt][2] + b0, acc[mt][nt][3] + b1);
            *reinterpret_cast<float2*>(y + (size_t)row       * NDIM + col) = v0;
            *reinterpret_cast<float2*>(y + (size_t)(row + 8) * NDIM + col) = v1;
        }
    }
}

// ------------------------------------------------------------------- host ----
extern "C" void kernel_launch(void* const* d_in, const int* in_sizes, int n_in,
                              void* d_out, int out_size) {
    const float* x      = (const float*)d_in[0];
    const float* values = (const float*)d_in[1];
    const int*   col    = (const int*)d_in[2];
    const float* bias   = (const float*)d_in[3];
    float* y = (float*)d_out;

    round_x_kernel<<<8192, 256>>>((const float4*)x);
    zero_w_kernel<<<8192, 256>>>();
    scatter_kernel<<<(NDIM * CAPQ + 255) / 256, 256>>>(values, col);

    static bool attr_set = false;
    if (!attr_set) {
        cudaFuncSetAttribute(gemm_kernel, cudaFuncAttributeMaxDynamicSharedMemorySize, SMEM_SIZE);
        attr_set = true;
    }
    gemm_kernel<<<MT * NT, 256, SMEM_SIZE>>>(bias, y);
}